// round 2
// baseline (speedup 1.0000x reference)
#include <cuda_runtime.h>
#include <cstddef>

#define I_DIM 256
#define R_DIM 64
#define O_DIM 256

// Scratch (allocation-free rule: __device__ globals)
__device__ float g_xsum[131072];
__device__ float g_wsum[R_DIM * O_DIM];

// ---------------------------------------------------------------------------
// Kernel 1: W_sum[r][o] = sum_i W[r][i][o].   64 blocks x 256 threads.
// Threads o=0..255 read consecutive addresses at each i -> fully coalesced.
// ---------------------------------------------------------------------------
__global__ void wsum_kernel(const float* __restrict__ W) {
    const int r = blockIdx.x;
    const int o = threadIdx.x;
    const float* p = W + (size_t)r * I_DIM * O_DIM + o;
    float s = 0.0f;
#pragma unroll 8
    for (int i = 0; i < I_DIM; ++i) s += p[(size_t)i * O_DIM];
    g_wsum[r * O_DIM + o] = s;
}

// ---------------------------------------------------------------------------
// Kernel 2: x_sum[e] = sum_j x[e][j].  One warp per row, float4 loads,
// warp shuffle reduction. Pure bandwidth (~102 MB read).
// ---------------------------------------------------------------------------
__global__ void xsum_kernel(const float* __restrict__ x, int E) {
    const int gw = (int)((blockIdx.x * (unsigned)blockDim.x + threadIdx.x) >> 5);
    const int lane = threadIdx.x & 31;
    if (gw >= E) return;
    const float4* p = reinterpret_cast<const float4*>(x + (size_t)gw * I_DIM);
    float4 a = p[lane];
    float4 b = p[lane + 32];
    float s = ((a.x + a.y) + (a.z + a.w)) + ((b.x + b.y) + (b.z + b.w));
#pragma unroll
    for (int off = 16; off; off >>= 1) s += __shfl_xor_sync(0xffffffffu, s, off);
    if (lane == 0) g_xsum[gw] = s;
}

// ---------------------------------------------------------------------------
// Kernel 3: out[e][o] = x_sum[e] * sum_r (1/cs[e][r]) * W_sum[r][o]
//
// Thread t owns output column t. W_sum column t is held in registers as 32
// packed f32x2 pairs over the r dimension (adjacent r values). The per-entity
// reciprocals are staged in shared (4 entities per iteration, double
// buffered, one __syncthreads per iteration) and consumed as broadcast
// LDS.64 pairs. Inner loop: 4 independent fma.rn.f32x2 chains (one per
// entity) -> 2 FMAs/instr, good ILP, LDS issues fill the rt=2 FMA gaps.
// ---------------------------------------------------------------------------
__device__ __forceinline__ void fma2(unsigned long long& d,
                                     unsigned long long a,
                                     unsigned long long b) {
    asm("fma.rn.f32x2 %0, %1, %2, %0;" : "+l"(d) : "l"(a), "l"(b));
}

__global__ void __launch_bounds__(256, 2) rgcn_main_kernel(
    const float* __restrict__ cs, float* __restrict__ out, int E) {
    __shared__ __align__(16) float rcs[2][256];
    const int t = threadIdx.x;

    // Load this thread's W_sum column as 32 packed (r, r+1) pairs.
    unsigned long long w2[32];
#pragma unroll
    for (int j = 0; j < 32; ++j) {
        float lo = g_wsum[(2 * j) * O_DIM + t];
        float hi = g_wsum[(2 * j + 1) * O_DIM + t];
        asm("mov.b64 %0, {%1, %2};" : "=l"(w2[j]) : "f"(lo), "f"(hi));
    }

    const int ngroups = (E + 3) >> 2;
    int buf = 0;
    for (int g = blockIdx.x; g < ngroups; g += gridDim.x) {
        const int ebase = g << 2;

        // Stage reciprocals for 4 entities: thread t handles entity t/64, r=t%64.
        {
            int e = ebase + (t >> 6);
            float c = (e < E) ? cs[(size_t)e * R_DIM + (t & 63)] : 1.0f;
            rcs[buf][t] = 1.0f / c;
        }
        __syncthreads();

        unsigned long long a0 = 0ull, a1 = 0ull, a2 = 0ull, a3 = 0ull;
        const unsigned long long* rp =
            reinterpret_cast<const unsigned long long*>(rcs[buf]);
#pragma unroll
        for (int j = 0; j < 32; ++j) {
            fma2(a0, rp[j],      w2[j]);
            fma2(a1, rp[32 + j], w2[j]);
            fma2(a2, rp[64 + j], w2[j]);
            fma2(a3, rp[96 + j], w2[j]);
        }

        float l0, h0, l1, h1, l2, h2, l3, h3;
        asm("mov.b64 {%0,%1}, %2;" : "=f"(l0), "=f"(h0) : "l"(a0));
        asm("mov.b64 {%0,%1}, %2;" : "=f"(l1), "=f"(h1) : "l"(a1));
        asm("mov.b64 {%0,%1}, %2;" : "=f"(l2), "=f"(h2) : "l"(a2));
        asm("mov.b64 {%0,%1}, %2;" : "=f"(l3), "=f"(h3) : "l"(a3));

        if (ebase + 0 < E) out[(size_t)(ebase + 0) * O_DIM + t] = (l0 + h0) * g_xsum[ebase + 0];
        if (ebase + 1 < E) out[(size_t)(ebase + 1) * O_DIM + t] = (l1 + h1) * g_xsum[ebase + 1];
        if (ebase + 2 < E) out[(size_t)(ebase + 2) * O_DIM + t] = (l2 + h2) * g_xsum[ebase + 2];
        if (ebase + 3 < E) out[(size_t)(ebase + 3) * O_DIM + t] = (l3 + h3) * g_xsum[ebase + 3];

        buf ^= 1;
        // No second barrier needed: double buffer; next write targets buf^1,
        // and a full barrier separates any two writes to the same buffer.
    }
}

// ---------------------------------------------------------------------------
// Launch. Inputs (metadata order): x (E*I f32), cs (E*R f32), W (R*I*O f32),
// edge_index (2*N int64, dead). Output: (E, O) f32.
// ---------------------------------------------------------------------------
extern "C" void kernel_launch(void* const* d_in, const int* in_sizes, int n_in,
                              void* d_out, int out_size) {
    const float* x  = (const float*)d_in[0];
    const float* cs = (const float*)d_in[1];
    const float* W  = (const float*)d_in[2];
    float* out = (float*)d_out;

    const int E = in_sizes[1] / R_DIM;

    wsum_kernel<<<R_DIM, O_DIM>>>(W);

    int xb = (E + 7) / 8;  // 8 warps (rows) per 256-thread block
    xsum_kernel<<<xb, 256>>>(x, E);

    const int ngroups = (E + 3) >> 2;
    int grid = 296;  // 2 CTAs/SM x 148 SMs; grid-stride, W_sum loaded once/block
    if (grid > ngroups) grid = ngroups;
    rgcn_main_kernel<<<grid, 256>>>(cs, out, E);
}

// round 3
// speedup vs baseline: 1.4403x; 1.4403x over previous
#include <cuda_runtime.h>
#include <cstddef>

#define I_DIM 256
#define R_DIM 64
#define O_DIM 256

// Scratch (allocation-free rule: __device__ global)
__device__ float g_wsum[R_DIM * O_DIM];

// ---------------------------------------------------------------------------
// W_sum[r][o] = sum_i W[r][i][o], parallelized 8x over the i dimension.
// zero kernel + 512 CTAs doing 32-row partials + one atomicAdd per thread.
// ---------------------------------------------------------------------------
__global__ void zero_wsum_kernel() {
    g_wsum[blockIdx.x * blockDim.x + threadIdx.x] = 0.0f;
}

__global__ void wsum_kernel(const float* __restrict__ W) {
    const int r = blockIdx.x;      // 0..63
    const int chunk = blockIdx.y;  // 0..7 -> i in [chunk*32, chunk*32+32)
    const int o = threadIdx.x;
    const float* p = W + ((size_t)r * I_DIM + chunk * 32) * O_DIM + o;
    float s = 0.0f;
#pragma unroll
    for (int i = 0; i < 32; ++i) s += p[(size_t)i * O_DIM];
    atomicAdd(&g_wsum[r * O_DIM + o], s);
}

// ---------------------------------------------------------------------------
// Main fused kernel:
//   out[e][o] = (sum_j x[e][j]) * sum_r (1/cs[e][r]) * W_sum[r][o]
//
// Thread t owns output column t; W_sum column lives in 32 packed f32x2 regs.
// Groups of 8 entities per iteration. Per group:
//   - prefetch next group's cs (2 loads/thread) + x rows (2 float4/warp-lane)
//     into registers BEFORE compute (hides DRAM latency)
//   - compute: 8 accumulator chains, LDS.128 (2 rcs pairs per load) feeding
//     2 fma.rn.f32x2 each -> 256 fma2 + only 128 LDS per thread
//   - stage prefetched data into the other shared buffer, one barrier/iter
// Chains processed 4+4 to keep live registers under the 128/2-CTA cap.
// ---------------------------------------------------------------------------
__device__ __forceinline__ void fma2(unsigned long long& d,
                                     unsigned long long a,
                                     unsigned long long b) {
    asm("fma.rn.f32x2 %0, %1, %2, %0;" : "+l"(d) : "l"(a), "l"(b));
}
__device__ __forceinline__ float frcp(float v) {
    float r; asm("rcp.approx.f32 %0, %1;" : "=f"(r) : "f"(v)); return r;
}

__global__ void __launch_bounds__(256, 2) rgcn_main_kernel(
    const float* __restrict__ x, const float* __restrict__ cs,
    float* __restrict__ out, int E, int ngroups) {
    __shared__ __align__(16) float rcs[2][512];  // 8 entities x 64 r
    __shared__ float xs[2][8];                   // 8 entity row-sums
    const int t = threadIdx.x;
    const int wid = t >> 5, lane = t & 31;

    // W_sum column t as 32 packed (r,r+1) pairs.
    unsigned long long w2[32];
#pragma unroll
    for (int j = 0; j < 32; ++j) {
        float lo = g_wsum[(2 * j) * O_DIM + t];
        float hi = g_wsum[(2 * j + 1) * O_DIM + t];
        asm("mov.b64 %0, {%1, %2};" : "=l"(w2[j]) : "f"(lo), "f"(hi));
    }

    int g = blockIdx.x;
    if (g >= ngroups) return;

    // Prologue: stage group g into buffer 0.
    {
        const int ebase = g << 3;
        int e0 = ebase + (t >> 6), e1 = ebase + 4 + (t >> 6);
        float c0 = (e0 < E) ? cs[(size_t)e0 * R_DIM + (t & 63)] : 1.0f;
        float c1 = (e1 < E) ? cs[(size_t)e1 * R_DIM + (t & 63)] : 1.0f;
        rcs[0][t] = frcp(c0);
        rcs[0][256 + t] = frcp(c1);
        int ex = ebase + wid;
        float s = 0.0f;
        if (ex < E) {
            const float4* xp = reinterpret_cast<const float4*>(x + (size_t)ex * I_DIM);
            float4 a = xp[lane], b = xp[lane + 32];
            s = ((a.x + a.y) + (a.z + a.w)) + ((b.x + b.y) + (b.z + b.w));
        }
#pragma unroll
        for (int off = 16; off; off >>= 1) s += __shfl_xor_sync(0xffffffffu, s, off);
        if (lane == 0) xs[0][wid] = s;
    }
    __syncthreads();

    int buf = 0;
    for (; g < ngroups; g += gridDim.x) {
        const int ebase = g << 3;
        const int gn = g + gridDim.x;

        // ---- prefetch next group into registers ----
        float c0 = 1.0f, c1 = 1.0f;
        float4 xa = make_float4(0.f, 0.f, 0.f, 0.f);
        float4 xb = make_float4(0.f, 0.f, 0.f, 0.f);
        if (gn < ngroups) {
            const int nbase = gn << 3;
            int e0 = nbase + (t >> 6), e1 = nbase + 4 + (t >> 6);
            if (e0 < E) c0 = cs[(size_t)e0 * R_DIM + (t & 63)];
            if (e1 < E) c1 = cs[(size_t)e1 * R_DIM + (t & 63)];
            int ex = nbase + wid;
            if (ex < E) {
                const float4* xp = reinterpret_cast<const float4*>(x + (size_t)ex * I_DIM);
                xa = xp[lane];
                xb = xp[lane + 32];
            }
        }

        // ---- compute current group: 8 chains in two halves of 4 ----
        const ulonglong2* rp = reinterpret_cast<const ulonglong2*>(rcs[buf]);
        unsigned long long acc[8];
#pragma unroll
        for (int k = 0; k < 8; ++k) acc[k] = 0ull;

#pragma unroll
        for (int j = 0; j < 16; ++j) {
            ulonglong2 p0 = rp[0 * 16 + j], p1 = rp[1 * 16 + j];
            ulonglong2 p2 = rp[2 * 16 + j], p3 = rp[3 * 16 + j];
            fma2(acc[0], p0.x, w2[2 * j]);
            fma2(acc[1], p1.x, w2[2 * j]);
            fma2(acc[2], p2.x, w2[2 * j]);
            fma2(acc[3], p3.x, w2[2 * j]);
            fma2(acc[0], p0.y, w2[2 * j + 1]);
            fma2(acc[1], p1.y, w2[2 * j + 1]);
            fma2(acc[2], p2.y, w2[2 * j + 1]);
            fma2(acc[3], p3.y, w2[2 * j + 1]);
        }
#pragma unroll
        for (int j = 0; j < 16; ++j) {
            ulonglong2 p4 = rp[4 * 16 + j], p5 = rp[5 * 16 + j];
            ulonglong2 p6 = rp[6 * 16 + j], p7 = rp[7 * 16 + j];
            fma2(acc[4], p4.x, w2[2 * j]);
            fma2(acc[5], p5.x, w2[2 * j]);
            fma2(acc[6], p6.x, w2[2 * j]);
            fma2(acc[7], p7.x, w2[2 * j]);
            fma2(acc[4], p4.y, w2[2 * j + 1]);
            fma2(acc[5], p5.y, w2[2 * j + 1]);
            fma2(acc[6], p6.y, w2[2 * j + 1]);
            fma2(acc[7], p7.y, w2[2 * j + 1]);
        }

        // ---- store ----
#pragma unroll
        for (int k = 0; k < 8; ++k) {
            int e = ebase + k;
            if (e < E) {
                float lo, hi;
                asm("mov.b64 {%0, %1}, %2;" : "=f"(lo), "=f"(hi) : "l"(acc[k]));
                out[(size_t)e * O_DIM + t] = (lo + hi) * xs[buf][k];
            }
        }

        // ---- stage prefetched data into the other buffer ----
        if (gn < ngroups) {
            rcs[buf ^ 1][t] = frcp(c0);
            rcs[buf ^ 1][256 + t] = frcp(c1);
            float s = ((xa.x + xa.y) + (xa.z + xa.w)) +
                      ((xb.x + xb.y) + (xb.z + xb.w));
#pragma unroll
            for (int off = 16; off; off >>= 1) s += __shfl_xor_sync(0xffffffffu, s, off);
            if (lane == 0) xs[buf ^ 1][wid] = s;
            __syncthreads();
        }
        buf ^= 1;
    }
}

// ---------------------------------------------------------------------------
// Launch. Inputs (metadata order): x (E*I f32), cs (E*R f32), W (R*I*O f32),
// edge_index (dead). Output: (E, O) f32.
// ---------------------------------------------------------------------------
extern "C" void kernel_launch(void* const* d_in, const int* in_sizes, int n_in,
                              void* d_out, int out_size) {
    const float* x  = (const float*)d_in[0];
    const float* cs = (const float*)d_in[1];
    const float* W  = (const float*)d_in[2];
    float* out = (float*)d_out;

    const int E = in_sizes[1] / R_DIM;

    zero_wsum_kernel<<<R_DIM, O_DIM>>>();
    dim3 wgrid(R_DIM, 8);
    wsum_kernel<<<wgrid, O_DIM>>>(W);

    const int ngroups = (E + 7) >> 3;
    int grid = 296;  // 2 CTAs/SM x 148 SMs
    if (grid > ngroups) grid = ngroups;
    rgcn_main_kernel<<<grid, 256>>>(x, cs, out, E, ngroups);
}